// round 1
// baseline (speedup 1.0000x reference)
#include <cuda_runtime.h>
#include <math.h>

#define NS 1024

// ---------------- scratch (no allocations allowed) ----------------
__device__ float g_h1p[NS*32*36*16];   // after stage1 pool
__device__ float g_h2p[NS*64*12*4];    // after stage2 pool
__device__ float g_h3p[NS*128*4*2];    // after stage3 pool (== flattened [S,1024])
__device__ float g_e [NS*128];
__device__ float g_q [NS*128];
__device__ float g_k [NS*128];
__device__ float g_v [NS*128];
__device__ float g_ao[NS*128];
__device__ float g_o2[NS*128];
__device__ float g_ea[NS*128];
__device__ float g_sq[NS];
__device__ unsigned int g_dmax;

__device__ __forceinline__ float selu_f(float x) {
    const float a = 1.6732632423543772f, sc = 1.0507009873554805f;
    return x > 0.f ? sc * x : sc * a * (expf(x) - 1.f);
}

// ============ Stage 1: conv(1->32,6x4) + SELU + GN(1ch/grp) + pool(2,4) ============
// grid (1024 frames, 32 channels), 256 threads
__global__ void k_conv1(const float* __restrict__ x, const float* __restrict__ w,
                        const float* __restrict__ bias, const float* __restrict__ gg,
                        const float* __restrict__ gb) {
    int s = blockIdx.x, c = blockIdx.y;
    __shared__ float pad[77*67];
    __shared__ float cv[72*64];
    __shared__ float wt[24];
    __shared__ float rs[8], rq[8];
    int tid = threadIdx.x;
    if (tid < 24) wt[tid] = w[c*24 + tid];
    const float* xs = x + s*4608;
    for (int i = tid; i < 77*67; i += 256) {
        int r = i / 67, cc = i - r*67;
        int ih = r - 2, iw = cc - 1;
        pad[i] = (ih >= 0 && ih < 72 && iw >= 0 && iw < 64) ? xs[ih*64 + iw] : 0.f;
    }
    __syncthreads();
    float bsum = 0.f, bsq = 0.f;
    float bi = bias[c];
    for (int p = tid; p < 4608; p += 256) {
        int oh = p >> 6, ow = p & 63;
        float acc = bi;
        #pragma unroll
        for (int kh = 0; kh < 6; kh++) {
            const float* pr = &pad[(oh+kh)*67 + ow];
            #pragma unroll
            for (int kw = 0; kw < 4; kw++) acc += pr[kw] * wt[kh*4 + kw];
        }
        acc = selu_f(acc);
        cv[p] = acc;
        bsum += acc; bsq += acc*acc;
    }
    #pragma unroll
    for (int o = 16; o; o >>= 1) {
        bsum += __shfl_down_sync(0xffffffffu, bsum, o);
        bsq  += __shfl_down_sync(0xffffffffu, bsq , o);
    }
    if ((tid & 31) == 0) { rs[tid>>5] = bsum; rq[tid>>5] = bsq; }
    __syncthreads();
    if (tid == 0) {
        float a = 0.f, b = 0.f;
        for (int i = 0; i < 8; i++) { a += rs[i]; b += rq[i]; }
        rs[0] = a; rq[0] = b;
    }
    __syncthreads();
    float mean = rs[0] * (1.f/4608.f);
    float var  = rq[0] * (1.f/4608.f) - mean*mean;
    float sc = gg[c] * rsqrtf(var + 1e-5f);
    float sh = gb[c] - mean * sc;
    for (int q = tid; q < 576; q += 256) {
        int ph = q >> 4, pw = q & 15;
        float m = -INFINITY;
        #pragma unroll
        for (int kh = 0; kh < 2; kh++)
            #pragma unroll
            for (int kw = 0; kw < 4; kw++)
                m = fmaxf(m, cv[(2*ph+kh)*64 + 4*pw+kw]*sc + sh);
        g_h1p[((s*32 + c)*36 + ph)*16 + pw] = m;
    }
}

// ============ Stage 2: conv(32->64,6x4) + SELU + GN(2ch/grp) + pool(3,4) ============
// grid (1024 frames, 32 groups), 192 threads, dyn smem = (24928+1152+1536)*4
__global__ void k_conv2(const float* __restrict__ w, const float* __restrict__ bias,
                        const float* __restrict__ gg, const float* __restrict__ gb) {
    extern __shared__ float sm2[];
    float* pad = sm2;               // 32*779
    float* cv  = sm2 + 24928;       // 2*576
    float* ws  = sm2 + 24928+1152;  // 2*32*24
    __shared__ float rs[6], rq[6];
    int s = blockIdx.x, g = blockIdx.y;
    int c0 = 2*g;
    int tid = threadIdx.x;  // 192
    for (int i = tid; i < 1536; i += 192) ws[i] = w[c0*768 + i];
    for (int i = tid; i < 32*779; i += 192) {
        int ch = i / 779; int rem = i - ch*779;
        int r = rem / 19, cc = rem - r*19;
        int ih = r - 2, iw = cc - 1;
        pad[i] = (ih >= 0 && ih < 36 && iw >= 0 && iw < 16)
               ? g_h1p[((s*32 + ch)*36 + ih)*16 + iw] : 0.f;
    }
    __syncthreads();
    float b0v = bias[c0], b1v = bias[c0+1];
    float a0[3] = {b0v, b0v, b0v};
    float a1[3] = {b1v, b1v, b1v};
    int offs[3];
    #pragma unroll
    for (int ii = 0; ii < 3; ii++) {
        int p = tid + 192*ii;
        int oh = p >> 4, ow = p & 15;
        offs[ii] = oh*19 + ow;
    }
    for (int ic = 0; ic < 32; ic++) {
        const float* pch = pad + ic*779;
        const float* w0 = ws + ic*24;
        const float* w1 = ws + 768 + ic*24;
        #pragma unroll
        for (int kh = 0; kh < 6; kh++) {
            float wa0 = w0[kh*4+0], wa1 = w0[kh*4+1], wa2 = w0[kh*4+2], wa3 = w0[kh*4+3];
            float wb0 = w1[kh*4+0], wb1 = w1[kh*4+1], wb2 = w1[kh*4+2], wb3 = w1[kh*4+3];
            #pragma unroll
            for (int ii = 0; ii < 3; ii++) {
                const float* pr = pch + offs[ii] + kh*19;
                float v0 = pr[0], v1 = pr[1], v2 = pr[2], v3 = pr[3];
                a0[ii] += v0*wa0 + v1*wa1 + v2*wa2 + v3*wa3;
                a1[ii] += v0*wb0 + v1*wb1 + v2*wb2 + v3*wb3;
            }
        }
    }
    float bsum = 0.f, bsq = 0.f;
    #pragma unroll
    for (int ii = 0; ii < 3; ii++) {
        int p = tid + 192*ii;
        float u0 = selu_f(a0[ii]), u1 = selu_f(a1[ii]);
        cv[p] = u0; cv[576 + p] = u1;
        bsum += u0 + u1; bsq += u0*u0 + u1*u1;
    }
    #pragma unroll
    for (int o = 16; o; o >>= 1) {
        bsum += __shfl_down_sync(0xffffffffu, bsum, o);
        bsq  += __shfl_down_sync(0xffffffffu, bsq , o);
    }
    if ((tid & 31) == 0) { rs[tid>>5] = bsum; rq[tid>>5] = bsq; }
    __syncthreads();
    if (tid == 0) {
        float a = 0.f, b = 0.f;
        for (int i = 0; i < 6; i++) { a += rs[i]; b += rq[i]; }
        rs[0] = a; rq[0] = b;
    }
    __syncthreads();
    float mean = rs[0] * (1.f/1152.f);
    float var  = rq[0] * (1.f/1152.f) - mean*mean;
    float inv  = rsqrtf(var + 1e-5f);
    if (tid < 96) {
        int ch = tid / 48; int rem = tid - ch*48;
        int ph = rem >> 2, pw = rem & 3;
        int c = c0 + ch;
        float sc = gg[c] * inv;
        float sh = gb[c] - mean * sc;
        float m = -INFINITY;
        #pragma unroll
        for (int kh = 0; kh < 3; kh++)
            #pragma unroll
            for (int kw = 0; kw < 4; kw++)
                m = fmaxf(m, cv[ch*576 + (3*ph+kh)*16 + 4*pw+kw]*sc + sh);
        g_h2p[((s*64 + c)*12 + ph)*4 + pw] = m;
    }
}

// ============ Stage 3: conv(64->128,6x4) + SELU + GN(4ch/grp) + pool(3,2) ============
// grid (1024 frames, 32 groups), 192 threads, dyn smem = (7616+192+6148)*4
__global__ void k_conv3(const float* __restrict__ w, const float* __restrict__ bias,
                        const float* __restrict__ gg, const float* __restrict__ gb) {
    extern __shared__ float sm3[];
    float* pad = sm3;               // 64*119 = 7616
    float* cv  = sm3 + 7616;        // 4*48
    float* ws  = sm3 + 7616 + 192;  // 4*1537 (padded rows)
    __shared__ float rs[6], rq[6];
    __shared__ float scs[4], shs[4];
    int s = blockIdx.x, g = blockIdx.y;
    int c0 = 4*g;
    int tid = threadIdx.x;  // 192
    for (int i = tid; i < 6144; i += 192) {
        int ch = i / 1536; int rem = i - ch*1536;
        ws[ch*1537 + rem] = w[c0*1536 + i];
    }
    for (int i = tid; i < 64*119; i += 192) {
        int ch = i / 119; int rem = i - ch*119;
        int r = rem / 7, cc = rem - r*7;
        int ih = r - 2, iw = cc - 1;
        pad[i] = (ih >= 0 && ih < 12 && iw >= 0 && iw < 4)
               ? g_h2p[((s*64 + ch)*12 + ih)*4 + iw] : 0.f;
    }
    __syncthreads();
    int pos = tid >> 2, ch = tid & 3;   // 48 positions x 4 channels
    int oh = pos >> 2, ow = pos & 3;
    float acc = bias[c0 + ch];
    const float* wch = ws + ch*1537;
    for (int ic = 0; ic < 64; ic++) {
        const float* pch = pad + ic*119 + oh*7 + ow;
        const float* wc = wch + ic*24;
        #pragma unroll
        for (int kh = 0; kh < 6; kh++)
            #pragma unroll
            for (int kw = 0; kw < 4; kw++)
                acc += pch[kh*7 + kw] * wc[kh*4 + kw];
    }
    acc = selu_f(acc);
    cv[ch*48 + pos] = acc;
    float bsum = acc, bsq = acc*acc;
    #pragma unroll
    for (int o = 16; o; o >>= 1) {
        bsum += __shfl_down_sync(0xffffffffu, bsum, o);
        bsq  += __shfl_down_sync(0xffffffffu, bsq , o);
    }
    if ((tid & 31) == 0) { rs[tid>>5] = bsum; rq[tid>>5] = bsq; }
    __syncthreads();
    if (tid == 0) {
        float a = 0.f, b = 0.f;
        for (int i = 0; i < 6; i++) { a += rs[i]; b += rq[i]; }
        rs[0] = a; rq[0] = b;
    }
    __syncthreads();
    float mean = rs[0] * (1.f/192.f);
    float var  = rq[0] * (1.f/192.f) - mean*mean;
    float inv  = rsqrtf(var + 1e-5f);
    if (tid < 4) {
        int c = c0 + tid;
        float sc = gg[c] * inv;
        scs[tid] = sc;
        shs[tid] = gb[c] - mean * sc;
    }
    __syncthreads();
    if (tid < 32) {
        int pch = tid >> 3; int rem = tid & 7;
        int ph = rem >> 1, pw = rem & 1;
        float sc = scs[pch], sh = shs[pch];
        float m = -INFINITY;
        #pragma unroll
        for (int kh = 0; kh < 3; kh++)
            #pragma unroll
            for (int kw = 0; kw < 2; kw++)
                m = fmaxf(m, cv[pch*48 + (3*ph+kh)*4 + 2*pw+kw]*sc + sh);
        g_h3p[((s*128 + c0 + pch)*4 + ph)*2 + pw] = m;
    }
}

// ============ FC: e = l2norm_row( selu( h3 @ W^T + b ) ) ============
// grid 1024, 128 threads
__global__ void k_fc(const float* __restrict__ w, const float* __restrict__ bias) {
    __shared__ float xr[1024];
    __shared__ float wt[128*65];   // padded stride 65
    __shared__ float rs[4];
    int s = blockIdx.x, tid = threadIdx.x;
    for (int i = tid; i < 1024; i += 128) xr[i] = g_h3p[s*1024 + i];
    float acc = bias[tid];
    for (int k0 = 0; k0 < 1024; k0 += 64) {
        __syncthreads();
        for (int i = tid; i < 8192; i += 128) {
            int j = i >> 6, kk = i & 63;
            wt[j*65 + kk] = w[j*1024 + k0 + kk];
        }
        __syncthreads();
        const float* wr = wt + tid*65;
        const float* xk = xr + k0;
        #pragma unroll
        for (int kk = 0; kk < 64; kk++) acc += xk[kk] * wr[kk];
    }
    acc = selu_f(acc);
    float ss = acc*acc;
    #pragma unroll
    for (int o = 16; o; o >>= 1) ss += __shfl_down_sync(0xffffffffu, ss, o);
    if ((tid & 31) == 0) rs[tid>>5] = ss;
    __syncthreads();
    float tot = rs[0] + rs[1] + rs[2] + rs[3];
    float n = fmaxf(sqrtf(tot), 1e-12f);
    g_e[s*128 + tid] = acc / n;
}

// ============ QKV + SELU, PE added to K ============
// grid 1024, 128 threads, dyn smem = 128*129*4
__global__ void k_qkv(const float* __restrict__ wq, const float* __restrict__ bq,
                      const float* __restrict__ wk, const float* __restrict__ bk,
                      const float* __restrict__ wv, const float* __restrict__ bv) {
    extern __shared__ float wt[];     // 128*129 padded
    __shared__ float er[128];
    int s = blockIdx.x, tid = threadIdx.x;
    er[tid] = g_e[s*128 + tid];
    // Q
    __syncthreads();
    for (int i = tid; i < 16384; i += 128) { int j = i >> 7, d = i & 127; wt[j*129 + d] = wq[i]; }
    __syncthreads();
    {
        float acc = bq[tid];
        const float* wr = wt + tid*129;
        #pragma unroll 8
        for (int d = 0; d < 128; d++) acc += er[d] * wr[d];
        g_q[s*128 + tid] = selu_f(acc);
    }
    // K (+PE)
    __syncthreads();
    for (int i = tid; i < 16384; i += 128) { int j = i >> 7, d = i & 127; wt[j*129 + d] = wk[i]; }
    __syncthreads();
    {
        float acc = bk[tid];
        const float* wr = wt + tid*129;
        #pragma unroll 8
        for (int d = 0; d < 128; d++) acc += er[d] * wr[d];
        acc = selu_f(acc);
        float t = (float)(tid & ~1);
        float f = expf(t * (-9.210340371976184f / 128.f));
        float ang = (float)s * f;
        acc += (tid & 1) ? cosf(ang) : sinf(ang);
        g_k[s*128 + tid] = acc;
    }
    // V
    __syncthreads();
    for (int i = tid; i < 16384; i += 128) { int j = i >> 7, d = i & 127; wt[j*129 + d] = wv[i]; }
    __syncthreads();
    {
        float acc = bv[tid];
        const float* wr = wt + tid*129;
        #pragma unroll 8
        for (int d = 0; d < 128; d++) acc += er[d] * wr[d];
        g_v[s*128 + tid] = selu_f(acc);
    }
}

// ============ attention: softmax(qK^T/sqrt(128)) @ V, fused per row ============
// grid 1024, 256 threads
__global__ void k_attn() {
    __shared__ __align__(16) float qr[128];
    __shared__ float p[1024];
    __shared__ float rs[8];
    __shared__ float part[128];
    int s = blockIdx.x, tid = threadIdx.x;
    if (tid < 128) qr[tid] = g_q[s*128 + tid];
    __syncthreads();
    const float scale = 0.08838834764831845f;  // 1/sqrt(128)
    float lmax = -INFINITY;
    for (int t = tid; t < 1024; t += 256) {
        const float4* kr = (const float4*)(g_k + t*128);
        const float4* q4 = (const float4*)qr;
        float acc = 0.f;
        #pragma unroll
        for (int d4 = 0; d4 < 32; d4++) {
            float4 kv = kr[d4];
            float4 qv = q4[d4];
            acc += qv.x*kv.x + qv.y*kv.y + qv.z*kv.z + qv.w*kv.w;
        }
        acc *= scale;
        p[t] = acc;
        lmax = fmaxf(lmax, acc);
    }
    #pragma unroll
    for (int o = 16; o; o >>= 1) lmax = fmaxf(lmax, __shfl_down_sync(0xffffffffu, lmax, o));
    if ((tid & 31) == 0) rs[tid>>5] = lmax;
    __syncthreads();
    float m = -INFINITY;
    for (int i = 0; i < 8; i++) m = fmaxf(m, rs[i]);
    float lsum = 0.f;
    for (int t = tid; t < 1024; t += 256) {
        float ev = expf(p[t] - m);
        p[t] = ev;
        lsum += ev;
    }
    __syncthreads();
    #pragma unroll
    for (int o = 16; o; o >>= 1) lsum += __shfl_down_sync(0xffffffffu, lsum, o);
    if ((tid & 31) == 0) rs[tid>>5] = lsum;
    __syncthreads();
    float tot = 0.f;
    for (int i = 0; i < 8; i++) tot += rs[i];
    float inv = 1.f / tot;
    // attn @ V : 256 threads = 128 cols x 2 halves of t-range
    int d = tid & 127, half = tid >> 7;
    float acc = 0.f;
    int t0 = half * 512;
    for (int t = t0; t < t0 + 512; t++) acc += p[t] * g_v[t*128 + d];
    if (half == 1) part[d] = acc;
    __syncthreads();
    if (half == 0) g_ao[s*128 + d] = (acc + part[d]) * inv;
}

// ============ column-wise l2norms: out = l2norm_col(ao)+e ; ea = l2norm_col(out) ============
// grid 1, 128 threads (one per column)
__global__ void k_colfix() {
    int d = threadIdx.x;
    float ss = 0.f;
    for (int s = 0; s < 1024; s++) { float v = g_ao[s*128 + d]; ss += v*v; }
    float inv1 = 1.f / fmaxf(sqrtf(ss), 1e-12f);
    float ss2 = 0.f;
    for (int s = 0; s < 1024; s++) {
        float v = g_ao[s*128 + d]*inv1 + g_e[s*128 + d];
        g_o2[s*128 + d] = v;
        ss2 += v*v;
    }
    float inv2 = 1.f / fmaxf(sqrtf(ss2), 1e-12f);
    for (int s = 0; s < 1024; s++) g_ea[s*128 + d] = g_o2[s*128 + d] * inv2;
}

// row sum-of-squares of ea
__global__ void k_rowsq() {
    int s = blockIdx.x*128 + threadIdx.x;
    const float4* r = (const float4*)(g_ea + s*128);
    float ss = 0.f;
    #pragma unroll
    for (int i = 0; i < 32; i++) {
        float4 v = r[i];
        ss += v.x*v.x + v.y*v.y + v.z*v.z + v.w*v.w;
    }
    g_sq[s] = ss;
}

__global__ void k_init() { g_dmax = 0u; }

// ============ pairwise distances d into d_out + global max ============
// grid (32,32), 256 threads (16x16), each thread computes a 2x2 microtile
__global__ void k_gram(float* __restrict__ dout) {
    __shared__ float ea_i[32][129];
    __shared__ float ea_j[32][129];
    __shared__ float sqi[32], sqj[32];
    __shared__ float rmax[8];
    int i0 = blockIdx.y * 32, j0 = blockIdx.x * 32;
    int tid = threadIdx.x;
    for (int idx = tid; idx < 4096; idx += 256) {
        int r = idx >> 7, d = idx & 127;
        ea_i[r][d] = g_ea[(i0+r)*128 + d];
        ea_j[r][d] = g_ea[(j0+r)*128 + d];
    }
    if (tid < 32) { sqi[tid] = g_sq[i0 + tid]; sqj[tid] = g_sq[j0 + tid]; }
    __syncthreads();
    int tx = tid & 15, ty = tid >> 4;
    int r0 = 2*ty, c0 = 2*tx;
    float d00 = 0.f, d01 = 0.f, d10 = 0.f, d11 = 0.f;
    #pragma unroll 4
    for (int d = 0; d < 128; d++) {
        float a0 = ea_i[r0][d], a1 = ea_i[r0+1][d];
        float b0 = ea_j[c0][d], b1 = ea_j[c0+1][d];
        d00 += a0*b0; d01 += a0*b1; d10 += a1*b0; d11 += a1*b1;
    }
    float lm = 0.f;
    float dots[4] = {d00, d01, d10, d11};
    #pragma unroll
    for (int u = 0; u < 4; u++) {
        int r = r0 + (u >> 1), c = c0 + (u & 1);
        float d2 = fmaxf(sqi[r] + sqj[c] - 2.f*dots[u], 0.f);
        float dd = sqrtf(d2 + 1e-12f);
        dout[(i0+r)*1024 + j0 + c] = dd;
        lm = fmaxf(lm, dd);
    }
    #pragma unroll
    for (int o = 16; o; o >>= 1) lm = fmaxf(lm, __shfl_down_sync(0xffffffffu, lm, o));
    if ((tid & 31) == 0) rmax[tid>>5] = lm;
    __syncthreads();
    if (tid == 0) {
        float m = 0.f;
        for (int i = 0; i < 8; i++) m = fmaxf(m, rmax[i]);
        atomicMax(&g_dmax, __float_as_uint(m));  // valid: all values >= 0
    }
}

__global__ void k_final(float* __restrict__ dout) {
    float inv = 1.f / __uint_as_float(g_dmax);
    int i = blockIdx.x*256 + threadIdx.x;
    dout[i] = 1.f - dout[i]*inv;
}

// ---------------- launcher ----------------
extern "C" void kernel_launch(void* const* d_in, const int* in_sizes, int n_in,
                              void* d_out, int out_size) {
    const float* x    = (const float*)d_in[0];
    const float* c1w  = (const float*)d_in[1];
    const float* c1b  = (const float*)d_in[2];
    const float* g1g  = (const float*)d_in[3];
    const float* g1b  = (const float*)d_in[4];
    const float* c2w  = (const float*)d_in[5];
    const float* c2b  = (const float*)d_in[6];
    const float* g2g  = (const float*)d_in[7];
    const float* g2b  = (const float*)d_in[8];
    const float* c3w  = (const float*)d_in[9];
    const float* c3b  = (const float*)d_in[10];
    const float* g3g  = (const float*)d_in[11];
    const float* g3b  = (const float*)d_in[12];
    const float* fcw  = (const float*)d_in[13];
    const float* fcb  = (const float*)d_in[14];
    const float* wq   = (const float*)d_in[15];
    const float* bq   = (const float*)d_in[16];
    const float* wk   = (const float*)d_in[17];
    const float* bk   = (const float*)d_in[18];
    const float* wv   = (const float*)d_in[19];
    const float* bv   = (const float*)d_in[20];
    float* out = (float*)d_out;

    cudaFuncSetAttribute(k_conv2, cudaFuncAttributeMaxDynamicSharedMemorySize, (24928+1152+1536)*4);
    cudaFuncSetAttribute(k_conv3, cudaFuncAttributeMaxDynamicSharedMemorySize, (7616+192+6148)*4);
    cudaFuncSetAttribute(k_qkv,   cudaFuncAttributeMaxDynamicSharedMemorySize, 128*129*4);

    k_conv1<<<dim3(1024,32), 256>>>(x, c1w, c1b, g1g, g1b);
    k_conv2<<<dim3(1024,32), 192, (24928+1152+1536)*4>>>(c2w, c2b, g2g, g2b);
    k_conv3<<<dim3(1024,32), 192, (7616+192+6148)*4>>>(c3w, c3b, g3g, g3b);
    k_fc  <<<1024, 128>>>(fcw, fcb);
    k_qkv <<<1024, 128, 128*129*4>>>(wq, bq, wk, bk, wv, bv);
    k_attn<<<1024, 256>>>();
    k_colfix<<<1, 128>>>();
    k_rowsq<<<8, 128>>>();
    k_init<<<1, 1>>>();
    k_gram<<<dim3(32,32), 256>>>(out);
    k_final<<<4096, 256>>>(out);
}